// round 10
// baseline (speedup 1.0000x reference)
#include <cuda_runtime.h>
#include <cuda_bf16.h>
#include <cstdint>
#include <math.h>

#define NTOK 8192
#define DIM  512
#define HID  1024
#define NEXP 16

// ---------------- device scratch (static globals; no allocation) -----------
// NOTE: these are ONLY referenced from device code (never passed as kernel
// arguments from host) — host-side decay of __device__ symbols is the bug
// that broke rounds 3/4/8.
__device__ int   g_cnt[NEXP];
__device__ int   g_tok [NEXP * NTOK];
__device__ int   g_slot[NEXP * NTOK];
__device__ float g_sscr[NTOK * 2];

// packed split format: word = hi_bf16 | (lo_bf16 << 16)
__device__ __align__(16) uint32_t g_xp [NTOK * DIM];            // x   [n][k]
__device__ __align__(16) uint32_t g_w1p[NEXP * HID * DIM];      // W1^T [e][n][k]
__device__ __align__(16) uint32_t g_w2p[NEXP * DIM * HID];      // W2^T [e][n][k]
__device__ __align__(16) uint32_t g_hp [NTOK * 2 * HID];        // h   [slot][k]
__device__ __align__(16) float    g_y  [NTOK * 2 * DIM];

// ---------------- mma / ldmatrix -------------------------------------------
#define MMA16816(d, a0, a1, a2, a3, b0, b1) \
    asm volatile("mma.sync.aligned.m16n8k16.row.col.f32.bf16.bf16.f32 " \
                 "{%0,%1,%2,%3}, {%4,%5,%6,%7}, {%8,%9}, {%0,%1,%2,%3};" \
                 : "+f"((d)[0]), "+f"((d)[1]), "+f"((d)[2]), "+f"((d)[3]) \
                 : "r"(a0), "r"(a1), "r"(a2), "r"(a3), "r"(b0), "r"(b1))

#define LDSM4(r0, r1, r2, r3, addr) \
    asm volatile("ldmatrix.sync.aligned.m8n8.x4.shared.b16 {%0,%1,%2,%3}, [%4];" \
                 : "=r"(r0), "=r"(r1), "=r"(r2), "=r"(r3) : "r"(addr))

__device__ __forceinline__ uint32_t smem_u32(const void* p) {
    uint32_t a;
    asm("{ .reg .u64 t; cvta.to.shared.u64 t, %1; cvt.u32.u64 %0, t; }" : "=r"(a) : "l"(p));
    return a;
}

__device__ __forceinline__ uint32_t packsplit(float v) {
    __nv_bfloat16 h = __float2bfloat16(v);
    __nv_bfloat16 l = __float2bfloat16(v - __bfloat162float(h));
    uint16_t hb = *(uint16_t*)&h, lb = *(uint16_t*)&l;
    return (uint32_t)hb | ((uint32_t)lb << 16);
}

// smem tile: 128 rows x 8 words (16 bf16), pitch 12 words (48B) -> conflict-free
#define PITCHW 12
#define PITCHB 48
#define TILE_W (128 * PITCHW)

// ---------------- routing ---------------------------------------------------
__global__ void k_reset() { if (threadIdx.x < NEXP) g_cnt[threadIdx.x] = 0; }

__global__ void k_route(const float* __restrict__ routing) {
    int n = blockIdx.x * blockDim.x + threadIdx.x;
    if (n >= NTOK) return;
    int j = 0;
    #pragma unroll
    for (int e = 0; e < NEXP; e++) {
        float s = routing[n * NEXP + e];
        if (s > 0.0f && j < 2) {
            int r = atomicAdd(&g_cnt[e], 1);
            g_tok [e * NTOK + r] = n;
            g_slot[e * NTOK + r] = n * 2 + j;
            g_sscr[n * 2 + j]    = s;
            j++;
        }
    }
    for (; j < 2; j++) g_sscr[n * 2 + j] = 0.0f;
}

// ---------------- precompute ------------------------------------------------
__global__ void k_split_x(const float* __restrict__ x) {
    int i = (blockIdx.x * blockDim.x + threadIdx.x) * 4;
    float4 v = *(const float4*)(x + i);
    *(uint4*)(g_xp + i) = make_uint4(packsplit(v.x), packsplit(v.y),
                                     packsplit(v.z), packsplit(v.w));
}

// transpose-convert-pack: W [e][R][C] fp32 -> out [e][C][R] packed
__device__ __forceinline__ void cvt_w_body(const float* __restrict__ W,
                                           uint32_t* __restrict__ outp,
                                           int R, int C) {
    __shared__ float t[32][33];
    int e = blockIdx.z;
    int c0 = blockIdx.x * 32, r0 = blockIdx.y * 32;
    int tx = threadIdx.x, ty = threadIdx.y;
    const float* Wb = W + (size_t)e * R * C;
    #pragma unroll
    for (int i = 0; i < 4; i++)
        t[ty + i * 8][tx] = Wb[(size_t)(r0 + ty + i * 8) * C + c0 + tx];
    __syncthreads();
    size_t ob = (size_t)e * C * R;
    #pragma unroll
    for (int i = 0; i < 4; i++) {
        float v = t[tx][ty + i * 8];
        outp[ob + (size_t)(c0 + ty + i * 8) * R + r0 + tx] = packsplit(v);
    }
}
__global__ void k_cvt_w1(const float* __restrict__ W) { cvt_w_body(W, g_w1p, DIM, HID); }
__global__ void k_cvt_w2(const float* __restrict__ W) { cvt_w_body(W, g_w2p, HID, DIM); }

// ---------------- core: 128x128 tile, packed operands -----------------------
// Every thread owns one row (A: tid 0-127, B: tid 128-255) and copies 16
// packed words (contiguous) per chunk; PRMT splits into hi/lo smem tiles.
__device__ __forceinline__ void mm_core(
    uint32_t* sAh, uint32_t* sAl, uint32_t* sBh, uint32_t* sBl,
    const uint32_t* rowP, int NC, float acc[2][8][4])
{
    const int tid = threadIdx.x;
    const int lid = tid & 31;
    const int wm = (tid >> 5) & 3, wn = tid >> 7;
    const bool isA = tid < 128;
    const int r = tid & 127;
    uint32_t* sH = isA ? sAh : sBh;
    uint32_t* sL = isA ? sAl : sBl;

    const uint32_t aAh = smem_u32(sAh), aAl = smem_u32(sAl);
    const uint32_t aBh = smem_u32(sBh), aBl = smem_u32(sBl);
    const uint32_t aoff = (uint32_t)(wm * 32 + (lid & 15)) * PITCHB + (uint32_t)(lid >> 4) * 16;
    const uint32_t boff = (uint32_t)(wn * 64 + (lid & 7) + ((lid >> 4) << 3)) * PITCHB
                        + (uint32_t)((lid >> 3) & 1) * 16;

    uint4 p0 = *(const uint4*)(rowP);
    uint4 p1 = *(const uint4*)(rowP + 4);
    uint4 p2 = *(const uint4*)(rowP + 8);
    uint4 p3 = *(const uint4*)(rowP + 12);

    for (int c = 0; c < NC; c++) {
        if (c > 0) __syncthreads();
        // split packed words: hw = (hi0, hi1), lw = (lo0, lo1) per pair
        uint32_t hw[8], lw[8];
        hw[0] = __byte_perm(p0.x, p0.y, 0x5410); lw[0] = __byte_perm(p0.x, p0.y, 0x7632);
        hw[1] = __byte_perm(p0.z, p0.w, 0x5410); lw[1] = __byte_perm(p0.z, p0.w, 0x7632);
        hw[2] = __byte_perm(p1.x, p1.y, 0x5410); lw[2] = __byte_perm(p1.x, p1.y, 0x7632);
        hw[3] = __byte_perm(p1.z, p1.w, 0x5410); lw[3] = __byte_perm(p1.z, p1.w, 0x7632);
        hw[4] = __byte_perm(p2.x, p2.y, 0x5410); lw[4] = __byte_perm(p2.x, p2.y, 0x7632);
        hw[5] = __byte_perm(p2.z, p2.w, 0x5410); lw[5] = __byte_perm(p2.z, p2.w, 0x7632);
        hw[6] = __byte_perm(p3.x, p3.y, 0x5410); lw[6] = __byte_perm(p3.x, p3.y, 0x7632);
        hw[7] = __byte_perm(p3.z, p3.w, 0x5410); lw[7] = __byte_perm(p3.z, p3.w, 0x7632);
        *(uint4*)&sH[r * PITCHW]     = make_uint4(hw[0], hw[1], hw[2], hw[3]);
        *(uint4*)&sH[r * PITCHW + 4] = make_uint4(hw[4], hw[5], hw[6], hw[7]);
        *(uint4*)&sL[r * PITCHW]     = make_uint4(lw[0], lw[1], lw[2], lw[3]);
        *(uint4*)&sL[r * PITCHW + 4] = make_uint4(lw[4], lw[5], lw[6], lw[7]);
        __syncthreads();

        if (c + 1 < NC) {
            int o = (c + 1) * 16;
            p0 = *(const uint4*)(rowP + o);
            p1 = *(const uint4*)(rowP + o + 4);
            p2 = *(const uint4*)(rowP + o + 8);
            p3 = *(const uint4*)(rowP + o + 12);
        }

        uint32_t Ah[2][4], Al[2][4];
        #pragma unroll
        for (int ma = 0; ma < 2; ma++) {
            LDSM4(Ah[ma][0], Ah[ma][1], Ah[ma][2], Ah[ma][3],
                  aAh + aoff + (uint32_t)(ma * 16 * PITCHB));
            LDSM4(Al[ma][0], Al[ma][1], Al[ma][2], Al[ma][3],
                  aAl + aoff + (uint32_t)(ma * 16 * PITCHB));
        }
        #pragma unroll
        for (int g2 = 0; g2 < 4; g2++) {
            uint32_t bh0, bh1, bh2, bh3, bl0, bl1, bl2, bl3;
            LDSM4(bh0, bh1, bh2, bh3, aBh + boff + (uint32_t)(g2 * 16 * PITCHB));
            LDSM4(bl0, bl1, bl2, bl3, aBl + boff + (uint32_t)(g2 * 16 * PITCHB));
            #pragma unroll
            for (int ma = 0; ma < 2; ma++) {
                MMA16816(acc[ma][2 * g2],     Ah[ma][0], Ah[ma][1], Ah[ma][2], Ah[ma][3], bh0, bh1);
                MMA16816(acc[ma][2 * g2],     Ah[ma][0], Ah[ma][1], Ah[ma][2], Ah[ma][3], bl0, bl1);
                MMA16816(acc[ma][2 * g2],     Al[ma][0], Al[ma][1], Al[ma][2], Al[ma][3], bh0, bh1);
                MMA16816(acc[ma][2 * g2 + 1], Ah[ma][0], Ah[ma][1], Ah[ma][2], Ah[ma][3], bh2, bh3);
                MMA16816(acc[ma][2 * g2 + 1], Ah[ma][0], Ah[ma][1], Ah[ma][2], Ah[ma][3], bl2, bl3);
                MMA16816(acc[ma][2 * g2 + 1], Al[ma][0], Al[ma][1], Al[ma][2], Al[ma][3], bh2, bh3);
            }
        }
    }
    __syncthreads();
}

// ---------------- GEMM1: h = gelu(x @ W1 + b1) -> packed g_hp ---------------
__global__ void __launch_bounds__(256, 2)
k_mm1(const float* __restrict__ b1)
{
    __shared__ __align__(16) uint32_t sAh[TILE_W], sAl[TILE_W], sBh[TILE_W], sBl[TILE_W];
    const int e   = blockIdx.z;
    const int cnt = g_cnt[e];
    const int m0  = blockIdx.y * 128;
    if (m0 >= cnt) return;
    const int n0  = blockIdx.x * 128;
    const int tid = threadIdx.x;
    const int lid = tid & 31;
    const int wm = (tid >> 5) & 3, wn = tid >> 7;
    const int r = tid & 127;

    const uint32_t* rowP;
    if (tid < 128) {
        const int tok = g_tok[e * NTOK + min(m0 + r, cnt - 1)];
        rowP = g_xp + (size_t)tok * DIM;
    } else {
        rowP = g_w1p + ((size_t)e * HID + n0 + r) * DIM;
    }

    float acc[2][8][4];
    #pragma unroll
    for (int i = 0; i < 2; i++)
        #pragma unroll
        for (int j = 0; j < 8; j++)
            #pragma unroll
            for (int q = 0; q < 4; q++) acc[i][j][q] = 0.0f;

    mm_core(sAh, sAl, sBh, sBl, rowP, DIM / 16, acc);

    // epilogue: bias + exact gelu -> packed split into g_hp
    const int gid = lid >> 2, tig = lid & 3;
    #pragma unroll
    for (int ma = 0; ma < 2; ma++) {
        #pragma unroll
        for (int hh = 0; hh < 2; hh++) {
            int rr = m0 + wm * 32 + ma * 16 + gid + hh * 8;
            if (rr < cnt) {
                int slot = g_slot[e * NTOK + rr];
                size_t cb = (size_t)slot * HID + n0 + wn * 64 + 2 * tig;
                const float* bb = b1 + e * HID + n0 + wn * 64 + 2 * tig;
                #pragma unroll
                for (int g = 0; g < 8; g++) {
                    float v0 = acc[ma][g][hh * 2 + 0] + bb[g * 8];
                    float v1 = acc[ma][g][hh * 2 + 1] + bb[g * 8 + 1];
                    v0 = 0.5f * v0 * (1.0f + erff(v0 * 0.70710678118654752f));
                    v1 = 0.5f * v1 * (1.0f + erff(v1 * 0.70710678118654752f));
                    *(uint2*)(g_hp + cb + g * 8) = make_uint2(packsplit(v0), packsplit(v1));
                }
            }
        }
    }
}

// ---------------- GEMM2: y = h @ W2 + b2 -> g_y -----------------------------
__global__ void __launch_bounds__(256, 2)
k_mm2(const float* __restrict__ b2)
{
    __shared__ __align__(16) uint32_t sAh[TILE_W], sAl[TILE_W], sBh[TILE_W], sBl[TILE_W];
    const int e   = blockIdx.z;
    const int cnt = g_cnt[e];
    const int m0  = blockIdx.y * 128;
    if (m0 >= cnt) return;
    const int n0  = blockIdx.x * 128;
    const int tid = threadIdx.x;
    const int lid = tid & 31;
    const int wm = (tid >> 5) & 3, wn = tid >> 7;
    const int r = tid & 127;

    const uint32_t* rowP;
    if (tid < 128) {
        const int slot0 = g_slot[e * NTOK + min(m0 + r, cnt - 1)];
        rowP = g_hp + (size_t)slot0 * HID;
    } else {
        rowP = g_w2p + ((size_t)e * DIM + n0 + r) * HID;
    }

    float acc[2][8][4];
    #pragma unroll
    for (int i = 0; i < 2; i++)
        #pragma unroll
        for (int j = 0; j < 8; j++)
            #pragma unroll
            for (int q = 0; q < 4; q++) acc[i][j][q] = 0.0f;

    mm_core(sAh, sAl, sBh, sBl, rowP, HID / 16, acc);

    // epilogue: bias -> fp32 g_y
    const int gid = lid >> 2, tig = lid & 3;
    #pragma unroll
    for (int ma = 0; ma < 2; ma++) {
        #pragma unroll
        for (int hh = 0; hh < 2; hh++) {
            int rr = m0 + wm * 32 + ma * 16 + gid + hh * 8;
            if (rr < cnt) {
                int slot = g_slot[e * NTOK + rr];
                float* oy = g_y + (size_t)slot * DIM + n0 + wn * 64 + 2 * tig;
                const float* bb = b2 + e * DIM + n0 + wn * 64 + 2 * tig;
                #pragma unroll
                for (int g = 0; g < 8; g++) {
                    float2 w;
                    w.x = acc[ma][g][hh * 2 + 0] + bb[g * 8];
                    w.y = acc[ma][g][hh * 2 + 1] + bb[g * 8 + 1];
                    *(float2*)(oy + g * 8) = w;
                }
            }
        }
    }
}

// ---------------- combine: out[n] = s0*y[2n] + s1*y[2n+1] -------------------
__global__ void k_combine(float* __restrict__ out) {
    int n = blockIdx.x;
    int t = threadIdx.x;
    float s0 = g_sscr[2 * n], s1 = g_sscr[2 * n + 1];
    float4 acc = make_float4(0.f, 0.f, 0.f, 0.f);
    if (s0 > 0.0f) {
        float4 a = *(const float4*)(g_y + (size_t)(2 * n) * DIM + t * 4);
        acc.x = s0 * a.x; acc.y = s0 * a.y; acc.z = s0 * a.z; acc.w = s0 * a.w;
    }
    if (s1 > 0.0f) {
        float4 b = *(const float4*)(g_y + (size_t)(2 * n + 1) * DIM + t * 4);
        acc.x += s1 * b.x; acc.y += s1 * b.y; acc.z += s1 * b.z; acc.w += s1 * b.w;
    }
    *(float4*)(out + (size_t)n * DIM + t * 4) = acc;
}

// ---------------- launch ----------------------------------------------------
extern "C" void kernel_launch(void* const* d_in, const int* in_sizes, int n_in,
                              void* d_out, int out_size)
{
    const float* x  = (const float*)d_in[0];
    const float* rt = (const float*)d_in[1];
    const float* W1 = (const float*)d_in[2];
    const float* b1 = (const float*)d_in[3];
    const float* W2 = (const float*)d_in[4];
    const float* b2 = (const float*)d_in[5];
    float* out = (float*)d_out;

    k_reset<<<1, 32>>>();
    k_route<<<NTOK / 256, 256>>>(rt);
    k_split_x<<<(NTOK * DIM) / 1024, 256>>>(x);
    k_cvt_w1<<<dim3(HID / 32, DIM / 32, NEXP), dim3(32, 8)>>>(W1);
    k_cvt_w2<<<dim3(DIM / 32, HID / 32, NEXP), dim3(32, 8)>>>(W2);
    k_mm1<<<dim3(HID / 128, NTOK / 128, NEXP), 256>>>(b1);
    k_mm2<<<dim3(DIM / 128, NTOK / 128, NEXP), 256>>>(b2);
    k_combine<<<NTOK, 128>>>(out);
}

// round 12
// speedup vs baseline: 1.1247x; 1.1247x over previous
#include <cuda_runtime.h>
#include <cuda_bf16.h>
#include <cstdint>
#include <math.h>

#define NTOK 8192
#define DIM  512
#define HID  1024
#define NEXP 16

// ---------------- device scratch (static globals; no allocation) -----------
// Referenced ONLY from device code (host-side decay of __device__ symbols
// broke rounds 3/4/8).
__device__ int   g_cnt[NEXP];
__device__ int   g_tok [NEXP * NTOK];
__device__ int   g_slot[NEXP * NTOK];
__device__ float g_sscr[NTOK * 2];

__device__ __align__(16) __nv_bfloat16 g_xh [NTOK * DIM];
__device__ __align__(16) __nv_bfloat16 g_xl [NTOK * DIM];
__device__ __align__(16) __nv_bfloat16 g_w1h[NEXP * HID * DIM];  // [e][n][k]
__device__ __align__(16) __nv_bfloat16 g_w1l[NEXP * HID * DIM];
__device__ __align__(16) __nv_bfloat16 g_w2h[NEXP * DIM * HID];  // [e][n][k]
__device__ __align__(16) __nv_bfloat16 g_w2l[NEXP * DIM * HID];
__device__ __align__(16) __nv_bfloat16 g_hh [NTOK * 2 * HID];
__device__ __align__(16) __nv_bfloat16 g_hl [NTOK * 2 * HID];
__device__ __align__(16) float         g_y  [NTOK * 2 * DIM];

// ---------------- ptx ------------------------------------------------------
#define MMA16816(d, a0, a1, a2, a3, b0, b1) \
    asm volatile("mma.sync.aligned.m16n8k16.row.col.f32.bf16.bf16.f32 " \
                 "{%0,%1,%2,%3}, {%4,%5,%6,%7}, {%8,%9}, {%0,%1,%2,%3};" \
                 : "+f"((d)[0]), "+f"((d)[1]), "+f"((d)[2]), "+f"((d)[3]) \
                 : "r"(a0), "r"(a1), "r"(a2), "r"(a3), "r"(b0), "r"(b1))

#define LDSM4(r0, r1, r2, r3, addr) \
    asm volatile("ldmatrix.sync.aligned.m8n8.x4.shared.b16 {%0,%1,%2,%3}, [%4];" \
                 : "=r"(r0), "=r"(r1), "=r"(r2), "=r"(r3) : "r"(addr))

#define CP16(dst, src) \
    asm volatile("cp.async.cg.shared.global [%0], [%1], 16;" :: "r"(dst), "l"(src))
#define CP_COMMIT() asm volatile("cp.async.commit_group;" ::: "memory")
#define CP_WAIT2()  asm volatile("cp.async.wait_group 2;" ::: "memory")
#define CP_WAIT0()  asm volatile("cp.async.wait_group 0;" ::: "memory")

__device__ __forceinline__ uint32_t smem_u32(const void* p) {
    uint32_t a;
    asm("{ .reg .u64 t; cvta.to.shared.u64 t, %1; cvt.u32.u64 %0, t; }" : "=r"(a) : "l"(p));
    return a;
}

// smem tile: 128 rows x 8 words (16 bf16), pitch 12 words (48B) -> conflict-free
#define PITCHW  12
#define PITCHB  48
#define TILE_W  (128 * PITCHW)
#define STAGE_W (4 * TILE_W)           // Ah, Al, Bh, Bl
#define NSTAGE  4
#define SMEM_BYTES (NSTAGE * STAGE_W * 4)   // 98304

// ---------------- routing ---------------------------------------------------
__global__ void k_reset() { if (threadIdx.x < NEXP) g_cnt[threadIdx.x] = 0; }

__global__ void k_route(const float* __restrict__ routing) {
    int n = blockIdx.x * blockDim.x + threadIdx.x;
    if (n >= NTOK) return;
    int j = 0;
    #pragma unroll
    for (int e = 0; e < NEXP; e++) {
        float s = routing[n * NEXP + e];
        if (s > 0.0f && j < 2) {
            int r = atomicAdd(&g_cnt[e], 1);
            g_tok [e * NTOK + r] = n;
            g_slot[e * NTOK + r] = n * 2 + j;
            g_sscr[n * 2 + j]    = s;
            j++;
        }
    }
    for (; j < 2; j++) g_sscr[n * 2 + j] = 0.0f;
}

// ---------------- precompute ------------------------------------------------
__global__ void k_split_x(const float* __restrict__ x) {
    int i = (blockIdx.x * blockDim.x + threadIdx.x) * 4;
    float4 v = *(const float4*)(x + i);
    float vv[4] = {v.x, v.y, v.z, v.w};
    __nv_bfloat16 h[4], l[4];
    #pragma unroll
    for (int q = 0; q < 4; q++) {
        h[q] = __float2bfloat16(vv[q]);
        l[q] = __float2bfloat16(vv[q] - __bfloat162float(h[q]));
    }
    *(__nv_bfloat162*)(g_xh + i)     = __halves2bfloat162(h[0], h[1]);
    *(__nv_bfloat162*)(g_xh + i + 2) = __halves2bfloat162(h[2], h[3]);
    *(__nv_bfloat162*)(g_xl + i)     = __halves2bfloat162(l[0], l[1]);
    *(__nv_bfloat162*)(g_xl + i + 2) = __halves2bfloat162(l[2], l[3]);
}

// transpose-convert: W [e][R][C] fp32 -> oh/ol [e][C][R] bf16
__device__ __forceinline__ void cvt_w_body(const float* __restrict__ W,
                                           __nv_bfloat16* __restrict__ oh,
                                           __nv_bfloat16* __restrict__ ol,
                                           int R, int C) {
    __shared__ float t[32][33];
    int e = blockIdx.z;
    int c0 = blockIdx.x * 32, r0 = blockIdx.y * 32;
    int tx = threadIdx.x, ty = threadIdx.y;
    const float* Wb = W + (size_t)e * R * C;
    #pragma unroll
    for (int i = 0; i < 4; i++)
        t[ty + i * 8][tx] = Wb[(size_t)(r0 + ty + i * 8) * C + c0 + tx];
    __syncthreads();
    size_t ob = (size_t)e * C * R;
    #pragma unroll
    for (int i = 0; i < 4; i++) {
        float v = t[tx][ty + i * 8];
        __nv_bfloat16 h = __float2bfloat16(v);
        __nv_bfloat16 l = __float2bfloat16(v - __bfloat162float(h));
        size_t o = ob + (size_t)(c0 + ty + i * 8) * R + r0 + tx;
        oh[o] = h; ol[o] = l;
    }
}
__global__ void k_cvt_w1(const float* __restrict__ W) { cvt_w_body(W, g_w1h, g_w1l, DIM, HID); }
__global__ void k_cvt_w2(const float* __restrict__ W) { cvt_w_body(W, g_w2h, g_w2l, HID, DIM); }

// ---------------- core: 128x128 tile, cp.async 4-stage pipeline -------------
// Thread owns one row (A: tid 0-127, B: tid 128-255); per chunk copies
// 32B hi + 32B lo via 4x cp.async.cg 16B.
__device__ __forceinline__ void mm_core(
    uint32_t* sm,
    const __nv_bfloat16* rowH, const __nv_bfloat16* rowL,
    int NC, float acc[2][8][4])
{
    const int tid = threadIdx.x;
    const int lid = tid & 31;
    const int wm = (tid >> 5) & 3, wn = tid >> 7;
    const bool isA = tid < 128;
    const int r = tid & 127;

    const uint32_t smb = smem_u32(sm);
    // this thread's cp.async dst (hi tile, lo tile) within a stage, bytes
    const uint32_t dH = smb + (uint32_t)((isA ? 0 : 2) * TILE_W + r * PITCHW) * 4;
    const uint32_t dL = smb + (uint32_t)((isA ? 1 : 3) * TILE_W + r * PITCHW) * 4;
    // ldmatrix offsets (bytes, within a stage)
    const uint32_t aoff = (uint32_t)(wm * 32 + (lid & 15)) * PITCHB + (uint32_t)(lid >> 4) * 16;
    const uint32_t boff = (uint32_t)(wn * 64 + (lid & 7) + ((lid >> 4) << 3)) * PITCHB
                        + (uint32_t)((lid >> 3) & 1) * 16;

    // prologue: issue chunks 0..NSTAGE-2
    #pragma unroll
    for (int s = 0; s < NSTAGE - 1; s++) {
        uint32_t sb = (uint32_t)(s * STAGE_W * 4);
        CP16(dH + sb,      rowH + s * 16);
        CP16(dH + sb + 16, rowH + s * 16 + 8);
        CP16(dL + sb,      rowL + s * 16);
        CP16(dL + sb + 16, rowL + s * 16 + 8);
        CP_COMMIT();
    }

    for (int c = 0; c < NC; c++) {
        CP_WAIT2();
        __syncthreads();

        const uint32_t stg = smb + (uint32_t)((c & (NSTAGE - 1)) * STAGE_W * 4);
        const uint32_t aAh = stg, aAl = stg + TILE_W * 4;
        const uint32_t aBh = stg + 2 * TILE_W * 4, aBl = stg + 3 * TILE_W * 4;

        uint32_t Ah[2][4], Al[2][4];
        #pragma unroll
        for (int ma = 0; ma < 2; ma++) {
            LDSM4(Ah[ma][0], Ah[ma][1], Ah[ma][2], Ah[ma][3],
                  aAh + aoff + (uint32_t)(ma * 16 * PITCHB));
            LDSM4(Al[ma][0], Al[ma][1], Al[ma][2], Al[ma][3],
                  aAl + aoff + (uint32_t)(ma * 16 * PITCHB));
        }
        #pragma unroll
        for (int g2 = 0; g2 < 4; g2++) {
            uint32_t bh0, bh1, bh2, bh3, bl0, bl1, bl2, bl3;
            LDSM4(bh0, bh1, bh2, bh3, aBh + boff + (uint32_t)(g2 * 16 * PITCHB));
            LDSM4(bl0, bl1, bl2, bl3, aBl + boff + (uint32_t)(g2 * 16 * PITCHB));
            #pragma unroll
            for (int ma = 0; ma < 2; ma++) {
                MMA16816(acc[ma][2 * g2],     Ah[ma][0], Ah[ma][1], Ah[ma][2], Ah[ma][3], bh0, bh1);
                MMA16816(acc[ma][2 * g2],     Ah[ma][0], Ah[ma][1], Ah[ma][2], Ah[ma][3], bl0, bl1);
                MMA16816(acc[ma][2 * g2],     Al[ma][0], Al[ma][1], Al[ma][2], Al[ma][3], bh0, bh1);
                MMA16816(acc[ma][2 * g2 + 1], Ah[ma][0], Ah[ma][1], Ah[ma][2], Ah[ma][3], bh2, bh3);
                MMA16816(acc[ma][2 * g2 + 1], Ah[ma][0], Ah[ma][1], Ah[ma][2], Ah[ma][3], bl2, bl3);
                MMA16816(acc[ma][2 * g2 + 1], Al[ma][0], Al[ma][1], Al[ma][2], Al[ma][3], bh2, bh3);
            }
        }

        // issue chunk c+NSTAGE-1 into stage (c-1)&3 (readers all passed barrier)
        int nc = c + NSTAGE - 1;
        if (nc < NC) {
            uint32_t sb = (uint32_t)((nc & (NSTAGE - 1)) * STAGE_W * 4);
            CP16(dH + sb,      rowH + nc * 16);
            CP16(dH + sb + 16, rowH + nc * 16 + 8);
            CP16(dL + sb,      rowL + nc * 16);
            CP16(dL + sb + 16, rowL + nc * 16 + 8);
        }
        CP_COMMIT();
    }
    CP_WAIT0();
    __syncthreads();
}

// ---------------- GEMM1: h = gelu(x @ W1 + b1) -> bf16 hi/lo ----------------
__global__ void __launch_bounds__(256, 2)
k_mm1(const float* __restrict__ b1)
{
    extern __shared__ __align__(16) uint32_t sm[];
    const int e   = blockIdx.z;
    const int cnt = g_cnt[e];
    const int m0  = blockIdx.y * 128;
    if (m0 >= cnt) return;
    const int n0  = blockIdx.x * 128;
    const int tid = threadIdx.x;
    const int lid = tid & 31;
    const int wm = (tid >> 5) & 3, wn = tid >> 7;
    const int r = tid & 127;

    const __nv_bfloat16 *rowH, *rowL;
    if (tid < 128) {
        const int tok = g_tok[e * NTOK + min(m0 + r, cnt - 1)];
        rowH = g_xh + (size_t)tok * DIM;
        rowL = g_xl + (size_t)tok * DIM;
    } else {
        const size_t br = (size_t)e * HID + n0 + r;
        rowH = g_w1h + br * DIM;
        rowL = g_w1l + br * DIM;
    }

    float acc[2][8][4];
    #pragma unroll
    for (int i = 0; i < 2; i++)
        #pragma unroll
        for (int j = 0; j < 8; j++)
            #pragma unroll
            for (int q = 0; q < 4; q++) acc[i][j][q] = 0.0f;

    mm_core(sm, rowH, rowL, DIM / 16, acc);

    // epilogue: bias + exact gelu -> bf16 hi/lo into g_hh/g_hl
    const int gid = lid >> 2, tig = lid & 3;
    #pragma unroll
    for (int ma = 0; ma < 2; ma++) {
        #pragma unroll
        for (int hh = 0; hh < 2; hh++) {
            int rr = m0 + wm * 32 + ma * 16 + gid + hh * 8;
            if (rr < cnt) {
                int slot = g_slot[e * NTOK + rr];
                size_t cb = (size_t)slot * HID + n0 + wn * 64 + 2 * tig;
                const float* bb = b1 + e * HID + n0 + wn * 64 + 2 * tig;
                #pragma unroll
                for (int g = 0; g < 8; g++) {
                    float v0 = acc[ma][g][hh * 2 + 0] + bb[g * 8];
                    float v1 = acc[ma][g][hh * 2 + 1] + bb[g * 8 + 1];
                    v0 = 0.5f * v0 * (1.0f + erff(v0 * 0.70710678118654752f));
                    v1 = 0.5f * v1 * (1.0f + erff(v1 * 0.70710678118654752f));
                    __nv_bfloat16 h0 = __float2bfloat16(v0);
                    __nv_bfloat16 h1 = __float2bfloat16(v1);
                    __nv_bfloat16 l0 = __float2bfloat16(v0 - __bfloat162float(h0));
                    __nv_bfloat16 l1 = __float2bfloat16(v1 - __bfloat162float(h1));
                    *(__nv_bfloat162*)(g_hh + cb + g * 8) = __halves2bfloat162(h0, h1);
                    *(__nv_bfloat162*)(g_hl + cb + g * 8) = __halves2bfloat162(l0, l1);
                }
            }
        }
    }
}

// ---------------- GEMM2: y = h @ W2 + b2 -> g_y -----------------------------
__global__ void __launch_bounds__(256, 2)
k_mm2(const float* __restrict__ b2)
{
    extern __shared__ __align__(16) uint32_t sm[];
    const int e   = blockIdx.z;
    const int cnt = g_cnt[e];
    const int m0  = blockIdx.y * 128;
    if (m0 >= cnt) return;
    const int n0  = blockIdx.x * 128;
    const int tid = threadIdx.x;
    const int lid = tid & 31;
    const int wm = (tid >> 5) & 3, wn = tid >> 7;
    const int r = tid & 127;

    const __nv_bfloat16 *rowH, *rowL;
    if (tid < 128) {
        const int slot0 = g_slot[e * NTOK + min(m0 + r, cnt - 1)];
        rowH = g_hh + (size_t)slot0 * HID;
        rowL = g_hl + (size_t)slot0 * HID;
    } else {
        const size_t br = (size_t)e * DIM + n0 + r;
        rowH = g_w2h + br * HID;
        rowL = g_w2l + br * HID;
    }

    float acc[2][8][4];
    #pragma unroll
    for (int i = 0; i < 2; i++)
        #pragma unroll
        for (int j = 0; j < 8; j++)
            #pragma unroll
            for (int q = 0; q < 4; q++) acc[i][j][q] = 0.0f;

    mm_core(sm, rowH, rowL, HID / 16, acc);

    // epilogue: bias -> fp32 g_y
    const int gid = lid >> 2, tig = lid & 3;
    #pragma unroll
    for (int ma = 0; ma < 2; ma++) {
        #pragma unroll
        for (int hh = 0; hh < 2; hh++) {
            int rr = m0 + wm * 32 + ma * 16 + gid + hh * 8;
            if (rr < cnt) {
                int slot = g_slot[e * NTOK + rr];
                float* oy = g_y + (size_t)slot * DIM + n0 + wn * 64 + 2 * tig;
                const float* bb = b2 + e * DIM + n0 + wn * 64 + 2 * tig;
                #pragma unroll
                for (int g = 0; g < 8; g++) {
                    float2 w;
                    w.x = acc[ma][g][hh * 2 + 0] + bb[g * 8];
                    w.y = acc[ma][g][hh * 2 + 1] + bb[g * 8 + 1];
                    *(float2*)(oy + g * 8) = w;
                }
            }
        }
    }
}

// ---------------- combine: out[n] = s0*y[2n] + s1*y[2n+1] -------------------
__global__ void k_combine(float* __restrict__ out) {
    int n = blockIdx.x;
    int t = threadIdx.x;
    float s0 = g_sscr[2 * n], s1 = g_sscr[2 * n + 1];
    float4 acc = make_float4(0.f, 0.f, 0.f, 0.f);
    if (s0 > 0.0f) {
        float4 a = *(const float4*)(g_y + (size_t)(2 * n) * DIM + t * 4);
        acc.x = s0 * a.x; acc.y = s0 * a.y; acc.z = s0 * a.z; acc.w = s0 * a.w;
    }
    if (s1 > 0.0f) {
        float4 b = *(const float4*)(g_y + (size_t)(2 * n + 1) * DIM + t * 4);
        acc.x += s1 * b.x; acc.y += s1 * b.y; acc.z += s1 * b.z; acc.w += s1 * b.w;
    }
    *(float4*)(out + (size_t)n * DIM + t * 4) = acc;
}

// ---------------- launch ----------------------------------------------------
extern "C" void kernel_launch(void* const* d_in, const int* in_sizes, int n_in,
                              void* d_out, int out_size)
{
    const float* x  = (const float*)d_in[0];
    const float* rt = (const float*)d_in[1];
    const float* W1 = (const float*)d_in[2];
    const float* b1 = (const float*)d_in[3];
    const float* W2 = (const float*)d_in[4];
    const float* b2 = (const float*)d_in[5];
    float* out = (float*)d_out;

    cudaFuncSetAttribute(k_mm1, cudaFuncAttributeMaxDynamicSharedMemorySize, SMEM_BYTES);
    cudaFuncSetAttribute(k_mm2, cudaFuncAttributeMaxDynamicSharedMemorySize, SMEM_BYTES);

    k_reset<<<1, 32>>>();
    k_route<<<NTOK / 256, 256>>>(rt);
    k_split_x<<<(NTOK * DIM) / 1024, 256>>>(x);
    k_cvt_w1<<<dim3(HID / 32, DIM / 32, NEXP), dim3(32, 8)>>>(W1);
    k_cvt_w2<<<dim3(DIM / 32, HID / 32, NEXP), dim3(32, 8)>>>(W2);
    k_mm1<<<dim3(HID / 128, NTOK / 128, NEXP), 256, SMEM_BYTES>>>(b1);
    k_mm2<<<dim3(DIM / 128, NTOK / 128, NEXP), 256, SMEM_BYTES>>>(b2);
    k_combine<<<NTOK, 128>>>(out);
}